// round 15
// baseline (speedup 1.0000x reference)
#include <cuda_runtime.h>

#define H_IMG 512
#define W_IMG 512
#define NMAX  2048
#define TILE  8
#define TX_N  (W_IMG / TILE)   /* 64 */
#define TY_N  (H_IMG / TILE)   /* 64 */
#define NTILES (TX_N * TY_N)   /* 4096 */
#define CAPN  1024             /* per-tile list capacity */
#define CHUNKW 64              /* per-warp staging chunk */

#define TWO_PI_F        6.28318530717958647692f
#define LOG2E_F         1.44269504088896340736f
#define LOG2_ALPHA_MIN  -7.99435344f    /* log2(1/255) */
#define E_CAP           254.745f        /* 0.999 * 255 */
#define FEAT_SCALE      0.003921568859f /* 1/255 */

// Per-gaussian precomputed parameters (pre-scaled)
__device__ float4 g_P0[NMAX];   // mx, my, A'(=-0.5*log2e*c0), B'(=-0.5*log2e*c2)
__device__ float4 g_P1[NMAX];   // C'(=-log2e*c1), L'(=log2(op)-LOG2_ALPHA_MIN), fr', fg'
__device__ float  g_FB[NMAX];   // fb'
// Per-tile gaussian index lists (8x8 lattice)
__device__ int    g_tile_cnt[NTILES];          // zero at load; render re-zeroes
__device__ int    g_tile_list[NTILES][CAPN];   // 16 MB static scratch

// One WARP per gaussian. Fast-math; tight per-axis AABB of the exact ellipse;
// exact ellipse-vs-box test per candidate 8x8 tile (convex quadratic edge minima).
__global__ __launch_bounds__(256)
void prep_bin_kernel(const float* __restrict__ xyz,
                     const float* __restrict__ scaling,
                     const float* __restrict__ rot,
                     const float* __restrict__ feat,
                     const float* __restrict__ opac,
                     int N)
{
    int warp = (blockIdx.x * blockDim.x + threadIdx.x) >> 5;
    int lane = threadIdx.x & 31;
    int i = warp;
    if (i >= N) return;

    float theta = (1.0f / (1.0f + __expf(-rot[i]))) * TWO_PI_F;
    float s0 = fabsf(scaling[2*i + 0]); s0 *= s0;
    float s1 = fabsf(scaling[2*i + 1]); s1 *= s1;
    float cs = __cosf(theta);
    float sn = __sinf(theta);

    float a = cs*cs*s0 + sn*sn*s1;     // Sigma_xx
    float b = cs*sn*(s0 - s1);         // Sigma_xy
    float c = sn*sn*s0 + cs*cs*s1;     // Sigma_yy
    float inv_det = 1.0f / (a*c - b*b);
    float c0 =  c * inv_det;
    float c1 = -b * inv_det;
    float c2 =  a * inv_det;

    float mx = 0.5f * ((xyz[2*i + 0] + 1.0f) * (float)W_IMG - 1.0f);
    float my = 0.5f * ((xyz[2*i + 1] + 1.0f) * (float)H_IMG - 1.0f);

    float op = opac[i];
    if (lane == 0) {
        g_P0[i] = make_float4(mx, my, -0.5f * LOG2E_F * c0, -0.5f * LOG2E_F * c2);
        g_P1[i] = make_float4(-LOG2E_F * c1, __log2f(op) - LOG2_ALPHA_MIN,
                              feat[3*i + 0] * FEAT_SCALE, feat[3*i + 1] * FEAT_SCALE);
        g_FB[i] = feat[3*i + 2] * FEAT_SCALE;
    }

    float lnthr = __logf(op * 255.0f);    // contributes iff sigma <= lnthr
    if (lnthr <= 0.0f) return;
    float thr = lnthr + 1e-2f;            // margin >> fp noise

    // sigma(d) = aq*dx^2 + bq*dx*dy + cq*dy^2
    float aq = 0.5f * c0;
    float bq = c1;
    float cq = 0.5f * c2;
    float inv2aq = 0.5f / aq;
    float inv2cq = 0.5f / cq;

    // tight per-axis extents of the exact ellipse {sigma <= thr}
    float rx = sqrtf(2.0f * thr * a);
    float ry = sqrtf(2.0f * thr * c);

    int tx_lo = max(0,        (int)floorf((mx - rx) * (1.0f / TILE)));
    int tx_hi = min(TX_N - 1, (int)floorf((mx + rx) * (1.0f / TILE)));
    int ty_lo = max(0,        (int)floorf((my - ry) * (1.0f / TILE)));
    int ty_hi = min(TY_N - 1, (int)floorf((my + ry) * (1.0f / TILE)));
    if (tx_hi < tx_lo || ty_hi < ty_lo) return;

    int w = tx_hi - tx_lo + 1;
    int cand = w * (ty_hi - ty_lo + 1);

    for (int sidx = lane; sidx < cand; sidx += 32) {
        int tx = tx_lo + (sidx % w);
        int ty = ty_lo + (sidx / w);
        float lx = (float)(tx * TILE) - mx;
        float hx = lx + (float)(TILE - 1);
        float ly = (float)(ty * TILE) - my;
        float hy = ly + (float)(TILE - 1);

        float smin;
        if (lx <= 0.0f && hx >= 0.0f && ly <= 0.0f && hy >= 0.0f) {
            smin = 0.0f;   // center inside box
        } else {
            float dyc = fminf(fmaxf(-bq * lx * inv2cq, ly), hy);
            float e0 = fmaf(cq * dyc, dyc, fmaf(bq * lx, dyc, aq * lx * lx));
            dyc = fminf(fmaxf(-bq * hx * inv2cq, ly), hy);
            float e1 = fmaf(cq * dyc, dyc, fmaf(bq * hx, dyc, aq * hx * hx));
            float dxc = fminf(fmaxf(-bq * ly * inv2aq, lx), hx);
            float e2 = fmaf(aq * dxc, dxc, fmaf(bq * ly, dxc, cq * ly * ly));
            dxc = fminf(fmaxf(-bq * hy * inv2aq, lx), hx);
            float e3 = fmaf(aq * dxc, dxc, fmaf(bq * hy, dxc, cq * hy * hy));
            smin = fminf(fminf(e0, e1), fminf(e2, e3));
        }

        if (smin <= thr) {
            int t = ty * TX_N + tx;
            int pos = atomicAdd(&g_tile_cnt[t], 1);
            if (pos < CAPN) g_tile_list[t][pos] = i;
        }
    }
}

// 128 threads = 4 independent WARPS, each owning one 8x8 tile (2 px/lane).
// Per-warp smem staging, __syncwarp only -- no CTA barriers, fine-grained
// balance across 4096 warp-sized work units. Single wave (8 CTAs/SM).
__global__ __launch_bounds__(128, 8)
void render_kernel(float* __restrict__ out)
{
    __shared__ float4 sP0[4][CHUNKW];
    __shared__ float4 sP1[4][CHUNKW];
    __shared__ float  sFB[4][CHUNKW];

    const int w    = threadIdx.x >> 5;
    const int lane = threadIdx.x & 31;
    const int tile = blockIdx.x * 4 + w;

    const int tx8 = tile & (TX_N - 1);
    const int ty8 = tile >> 6;
    const int px  = tx8 * TILE + (lane & 7);
    const int py0 = ty8 * TILE + (lane >> 3);   // rows 0..3
    const int py1 = py0 + 4;                    // rows 4..7
    const float fx  = (float)px;
    const float fy0 = (float)py0;

    int cnt = g_tile_cnt[tile];
    if (cnt > CAPN) cnt = CAPN;
    if (lane == 0) g_tile_cnt[tile] = 0;   // leave zeroed for next launch

    float r0a = 0.0f, g0a = 0.0f, b0a = 0.0f;   // (px, py0)
    float r1a = 0.0f, g1a = 0.0f, b1a = 0.0f;   // (px, py1)

    for (int base = 0; base < cnt; base += CHUNKW) {
        int m = cnt - base;
        if (m > CHUNKW) m = CHUNKW;

        for (int k = lane; k < m; k += 32) {
            int gi = g_tile_list[tile][base + k];
            sP0[w][k] = g_P0[gi];
            sP1[w][k] = g_P1[gi];
            sFB[w][k] = g_FB[gi];
        }
        __syncwarp();

        #pragma unroll 2
        for (int j = 0; j < m; ++j) {
            float4 qa = sP0[w][j];
            float4 qb = sP1[w][j];
            float  qc = sFB[w][j];

            float dx  = fx - qa.x;
            float dy0 = fy0 - qa.y;
            float dy1 = dy0 + 4.0f;

            float adx = qa.z * dx;                    // A'*dx (shared)
            float rt0 = fmaf(qa.w * dy0, dy0, qb.y);  // B'*dy^2 + L'
            float rt1 = fmaf(qa.w * dy1, dy1, qb.y);
            float t0  = fmaf(qb.x, dy0, adx);
            float t1  = fmaf(qb.x, dy1, adx);
            float b0  = fmaf(t0, dx, rt0);
            float b1  = fmaf(t1, dx, rt1);

            // e = 2^arg = alpha*255 ; clamp at 0.999*255 ; skip if arg<0
            float e0, e1;
            asm("ex2.approx.ftz.f32 %0, %1;" : "=f"(e0) : "f"(b0));
            asm("ex2.approx.ftz.f32 %0, %1;" : "=f"(e1) : "f"(b1));
            e0 = fminf(e0, E_CAP);
            e1 = fminf(e1, E_CAP);

            if (b0 >= 0.0f) {
                r0a = fmaf(e0, qb.z, r0a);
                g0a = fmaf(e0, qb.w, g0a);
                b0a = fmaf(e0, qc,   b0a);
            }
            if (b1 >= 0.0f) {
                r1a = fmaf(e1, qb.z, r1a);
                g1a = fmaf(e1, qb.w, g1a);
                b1a = fmaf(e1, qc,   b1a);
            }
        }
        __syncwarp();
    }

    // out layout: [1, 3, H, W]
    out[(0 * H_IMG + py0) * W_IMG + px] = fminf(fmaxf(r0a, 0.0f), 1.0f);
    out[(0 * H_IMG + py1) * W_IMG + px] = fminf(fmaxf(r1a, 0.0f), 1.0f);
    out[(1 * H_IMG + py0) * W_IMG + px] = fminf(fmaxf(g0a, 0.0f), 1.0f);
    out[(1 * H_IMG + py1) * W_IMG + px] = fminf(fmaxf(g1a, 0.0f), 1.0f);
    out[(2 * H_IMG + py0) * W_IMG + px] = fminf(fmaxf(b0a, 0.0f), 1.0f);
    out[(2 * H_IMG + py1) * W_IMG + px] = fminf(fmaxf(b1a, 0.0f), 1.0f);
}

extern "C" void kernel_launch(void* const* d_in, const int* in_sizes, int n_in,
                              void* d_out, int out_size)
{
    const float* xyz     = (const float*)d_in[0];
    const float* scaling = (const float*)d_in[1];
    const float* rot     = (const float*)d_in[2];
    const float* feat    = (const float*)d_in[3];
    const float* opac    = (const float*)d_in[4];
    float* out = (float*)d_out;

    int N = in_sizes[0] / 2;
    if (N > NMAX) N = NMAX;

    // one warp per gaussian
    prep_bin_kernel<<<(N * 32 + 255) / 256, 256>>>(xyz, scaling, rot, feat, opac, N);

    // 4 tiles (one per warp) per CTA; 4096 tiles total
    render_kernel<<<NTILES / 4, 128>>>(out);
}

// round 16
// speedup vs baseline: 1.1379x; 1.1379x over previous
#include <cuda_runtime.h>

#define H_IMG 512
#define W_IMG 512
#define NMAX  2048
#define TILE  16
#define TX_N  (W_IMG / TILE)   /* 32 */
#define TY_N  (H_IMG / TILE)   /* 32 */
#define NTILES (TX_N * TY_N)   /* 1024 */
#define CHUNK 256

#define TWO_PI_F        6.28318530717958647692f
#define LOG2E_F         1.44269504088896340736f
#define LOG2_ALPHA_MIN  -7.99435344f    /* log2(1/255) */
#define E_CAP           254.745f        /* 0.999 * 255 */
#define FEAT_SCALE      0.003921568859f /* 1/255 */

// Per-gaussian precomputed parameters (pre-scaled)
__device__ float4 g_P0[NMAX];   // mx, my, A'(=-0.5*log2e*c0), B'(=-0.5*log2e*c2)
__device__ float4 g_P1[NMAX];   // C'(=-log2e*c1), L'(=log2(op)-LOG2_ALPHA_MIN), fr', fg'
__device__ float  g_FB[NMAX];   // fb'
// Per-tile gaussian index lists
__device__ int    g_tile_cnt[NTILES];          // zero at load; render re-zeroes
__device__ int    g_tile_list[NTILES][NMAX];   // 8 MB static scratch

// One WARP per gaussian. Fast-math; tight per-axis AABB; exact ellipse-vs-box
// cull per candidate tile. Triggers programmatic launch completion at the end
// so the PDL-launched render overlaps its launch latency with this kernel.
__global__ __launch_bounds__(256)
void prep_bin_kernel(const float* __restrict__ xyz,
                     const float* __restrict__ scaling,
                     const float* __restrict__ rot,
                     const float* __restrict__ feat,
                     const float* __restrict__ opac,
                     int N)
{
    int warp = (blockIdx.x * blockDim.x + threadIdx.x) >> 5;
    int lane = threadIdx.x & 31;
    int i = warp;
    if (i < N) {
        float theta = (1.0f / (1.0f + __expf(-rot[i]))) * TWO_PI_F;
        float s0 = fabsf(scaling[2*i + 0]); s0 *= s0;
        float s1 = fabsf(scaling[2*i + 1]); s1 *= s1;
        float cs = __cosf(theta);
        float sn = __sinf(theta);

        float a = cs*cs*s0 + sn*sn*s1;     // Sigma_xx
        float b = cs*sn*(s0 - s1);         // Sigma_xy
        float c = sn*sn*s0 + cs*cs*s1;     // Sigma_yy
        float inv_det = 1.0f / (a*c - b*b);
        float c0 =  c * inv_det;
        float c1 = -b * inv_det;
        float c2 =  a * inv_det;

        float mx = 0.5f * ((xyz[2*i + 0] + 1.0f) * (float)W_IMG - 1.0f);
        float my = 0.5f * ((xyz[2*i + 1] + 1.0f) * (float)H_IMG - 1.0f);

        float op = opac[i];
        if (lane == 0) {
            g_P0[i] = make_float4(mx, my, -0.5f * LOG2E_F * c0, -0.5f * LOG2E_F * c2);
            g_P1[i] = make_float4(-LOG2E_F * c1, __log2f(op) - LOG2_ALPHA_MIN,
                                  feat[3*i + 0] * FEAT_SCALE, feat[3*i + 1] * FEAT_SCALE);
            g_FB[i] = feat[3*i + 2] * FEAT_SCALE;
        }

        float lnthr = __logf(op * 255.0f);    // contributes iff sigma <= lnthr
        if (lnthr > 0.0f) {
            float thr = lnthr + 1e-2f;        // margin >> fp noise

            // sigma(d) = aq*dx^2 + bq*dx*dy + cq*dy^2
            float aq = 0.5f * c0;
            float bq = c1;
            float cq = 0.5f * c2;
            float inv2aq = 0.5f / aq;
            float inv2cq = 0.5f / cq;

            // tight per-axis extents of the exact ellipse {sigma <= thr}
            float rx = sqrtf(2.0f * thr * a);
            float ry = sqrtf(2.0f * thr * c);

            int tx_lo = max(0,        (int)floorf((mx - rx) * (1.0f / TILE)));
            int tx_hi = min(TX_N - 1, (int)floorf((mx + rx) * (1.0f / TILE)));
            int ty_lo = max(0,        (int)floorf((my - ry) * (1.0f / TILE)));
            int ty_hi = min(TY_N - 1, (int)floorf((my + ry) * (1.0f / TILE)));

            if (tx_hi >= tx_lo && ty_hi >= ty_lo) {
                int w = tx_hi - tx_lo + 1;
                int cand = w * (ty_hi - ty_lo + 1);

                for (int sidx = lane; sidx < cand; sidx += 32) {
                    int tx = tx_lo + (sidx % w);
                    int ty = ty_lo + (sidx / w);
                    float lx = (float)(tx * TILE) - mx;
                    float hx = lx + (float)(TILE - 1);
                    float ly = (float)(ty * TILE) - my;
                    float hy = ly + (float)(TILE - 1);

                    float smin;
                    if (lx <= 0.0f && hx >= 0.0f && ly <= 0.0f && hy >= 0.0f) {
                        smin = 0.0f;   // center inside box
                    } else {
                        float dyc = fminf(fmaxf(-bq * lx * inv2cq, ly), hy);
                        float e0 = fmaf(cq * dyc, dyc, fmaf(bq * lx, dyc, aq * lx * lx));
                        dyc = fminf(fmaxf(-bq * hx * inv2cq, ly), hy);
                        float e1 = fmaf(cq * dyc, dyc, fmaf(bq * hx, dyc, aq * hx * hx));
                        float dxc = fminf(fmaxf(-bq * ly * inv2aq, lx), hx);
                        float e2 = fmaf(aq * dxc, dxc, fmaf(bq * ly, dxc, cq * ly * ly));
                        dxc = fminf(fmaxf(-bq * hy * inv2aq, lx), hx);
                        float e3 = fmaf(aq * dxc, dxc, fmaf(bq * hy, dxc, cq * hy * hy));
                        smin = fminf(fminf(e0, e1), fminf(e2, e3));
                    }

                    if (smin <= thr) {
                        int t = ty * TX_N + tx;
                        int pos = atomicAdd(&g_tile_cnt[t], 1);
                        g_tile_list[t][pos] = i;
                    }
                }
            }
        }
    }

#if __CUDA_ARCH__ >= 900
    cudaTriggerProgrammaticLaunchCompletion();
#endif
}

// 64 threads/CTA, each thread renders a 2x2 quad at stride 8 (measured-best R9).
// PDL secondary: CTAs launch while prep_bin still runs; the grid-dependency
// sync provides the ordered (and flushed) handoff with zero software spinning.
__global__ __launch_bounds__(64, 8)
void render_kernel(float* __restrict__ out)
{
    __shared__ float4 sP0[CHUNK];
    __shared__ float4 sP1[CHUNK];
    __shared__ float  sFB[CHUNK];

    const int tid = threadIdx.x;
    const int tx  = tid & 7;
    const int ty  = tid >> 3;

    const int tile = blockIdx.y * TX_N + blockIdx.x;
    const int px0 = blockIdx.x * TILE + tx;
    const int py0 = blockIdx.y * TILE + ty;
    const float fx0 = (float)px0;
    const float fy0 = (float)py0;

#if __CUDA_ARCH__ >= 900
    cudaGridDependencySynchronize();
#endif

    const int cnt = g_tile_cnt[tile];

    float a00r = 0.0f, a00g = 0.0f, a00b = 0.0f;   // (x, y)
    float a10r = 0.0f, a10g = 0.0f, a10b = 0.0f;   // (x+8, y)
    float a01r = 0.0f, a01g = 0.0f, a01b = 0.0f;   // (x, y+8)
    float a11r = 0.0f, a11g = 0.0f, a11b = 0.0f;   // (x+8, y+8)

    for (int base = 0; base < cnt; base += CHUNK) {
        int m = cnt - base;
        if (m > CHUNK) m = CHUNK;

        for (int k2 = tid; k2 < m; k2 += 64) {
            int g = g_tile_list[tile][base + k2];
            sP0[k2] = g_P0[g];
            sP1[k2] = g_P1[g];
            sFB[k2] = g_FB[g];
        }
        __syncthreads();

        #pragma unroll 2
        for (int j = 0; j < m; ++j) {
            float4 qa = sP0[j];
            float4 qb = sP1[j];
            float  qc = sFB[j];

            float dx0 = fx0 - qa.x, dx1 = dx0 + 8.0f;
            float dy0 = fy0 - qa.y, dy1 = dy0 + 8.0f;

            float adx0 = qa.z * dx0;                  // A'*dx  (per column)
            float adx1 = qa.z * dx1;
            float rt0  = fmaf(qa.w * dy0, dy0, qb.y); // B'*dy^2 + L' (per row)
            float rt1  = fmaf(qa.w * dy1, dy1, qb.y);

            float t00 = fmaf(qb.x, dy0, adx0);
            float t10 = fmaf(qb.x, dy0, adx1);
            float t01 = fmaf(qb.x, dy1, adx0);
            float t11 = fmaf(qb.x, dy1, adx1);
            float b00 = fmaf(t00, dx0, rt0);
            float b10 = fmaf(t10, dx1, rt0);
            float b01 = fmaf(t01, dx0, rt1);
            float b11 = fmaf(t11, dx1, rt1);

            // e = 2^arg = alpha*255 ; clamp at 0.999*255 ; skip if arg<0
            float e00, e10, e01, e11;
            asm("ex2.approx.ftz.f32 %0, %1;" : "=f"(e00) : "f"(b00));
            asm("ex2.approx.ftz.f32 %0, %1;" : "=f"(e10) : "f"(b10));
            asm("ex2.approx.ftz.f32 %0, %1;" : "=f"(e01) : "f"(b01));
            asm("ex2.approx.ftz.f32 %0, %1;" : "=f"(e11) : "f"(b11));
            e00 = fminf(e00, E_CAP);
            e10 = fminf(e10, E_CAP);
            e01 = fminf(e01, E_CAP);
            e11 = fminf(e11, E_CAP);

            if (b00 >= 0.0f) {
                a00r = fmaf(e00, qb.z, a00r);
                a00g = fmaf(e00, qb.w, a00g);
                a00b = fmaf(e00, qc,   a00b);
            }
            if (b10 >= 0.0f) {
                a10r = fmaf(e10, qb.z, a10r);
                a10g = fmaf(e10, qb.w, a10g);
                a10b = fmaf(e10, qc,   a10b);
            }
            if (b01 >= 0.0f) {
                a01r = fmaf(e01, qb.z, a01r);
                a01g = fmaf(e01, qb.w, a01g);
                a01b = fmaf(e01, qc,   a01b);
            }
            if (b11 >= 0.0f) {
                a11r = fmaf(e11, qb.z, a11r);
                a11g = fmaf(e11, qb.w, a11g);
                a11b = fmaf(e11, qc,   a11b);
            }
        }
        __syncthreads();
    }

    if (tid == 0) g_tile_cnt[tile] = 0;   // leave zeroed for next launch

    const int px1 = px0 + 8;
    const int py1 = py0 + 8;
    // out layout: [1, 3, H, W]
    out[(0 * H_IMG + py0) * W_IMG + px0] = fminf(fmaxf(a00r, 0.0f), 1.0f);
    out[(0 * H_IMG + py0) * W_IMG + px1] = fminf(fmaxf(a10r, 0.0f), 1.0f);
    out[(0 * H_IMG + py1) * W_IMG + px0] = fminf(fmaxf(a01r, 0.0f), 1.0f);
    out[(0 * H_IMG + py1) * W_IMG + px1] = fminf(fmaxf(a11r, 0.0f), 1.0f);
    out[(1 * H_IMG + py0) * W_IMG + px0] = fminf(fmaxf(a00g, 0.0f), 1.0f);
    out[(1 * H_IMG + py0) * W_IMG + px1] = fminf(fmaxf(a10g, 0.0f), 1.0f);
    out[(1 * H_IMG + py1) * W_IMG + px0] = fminf(fmaxf(a01g, 0.0f), 1.0f);
    out[(1 * H_IMG + py1) * W_IMG + px1] = fminf(fmaxf(a11g, 0.0f), 1.0f);
    out[(2 * H_IMG + py0) * W_IMG + px0] = fminf(fmaxf(a00b, 0.0f), 1.0f);
    out[(2 * H_IMG + py0) * W_IMG + px1] = fminf(fmaxf(a10b, 0.0f), 1.0f);
    out[(2 * H_IMG + py1) * W_IMG + px0] = fminf(fmaxf(a01b, 0.0f), 1.0f);
    out[(2 * H_IMG + py1) * W_IMG + px1] = fminf(fmaxf(a11b, 0.0f), 1.0f);
}

extern "C" void kernel_launch(void* const* d_in, const int* in_sizes, int n_in,
                              void* d_out, int out_size)
{
    const float* xyz     = (const float*)d_in[0];
    const float* scaling = (const float*)d_in[1];
    const float* rot     = (const float*)d_in[2];
    const float* feat    = (const float*)d_in[3];
    const float* opac    = (const float*)d_in[4];
    float* out = (float*)d_out;

    int N = in_sizes[0] / 2;
    if (N > NMAX) N = NMAX;

    // primary: one warp per gaussian
    prep_bin_kernel<<<(N * 32 + 255) / 256, 256>>>(xyz, scaling, rot, feat, opac, N);

    // secondary via PDL: launch overhead overlaps with prep_bin execution
    cudaLaunchConfig_t cfg = {};
    cfg.gridDim  = dim3(TX_N, TY_N, 1);
    cfg.blockDim = dim3(64, 1, 1);
    cfg.dynamicSmemBytes = 0;
    cudaLaunchAttribute attrs[1];
    attrs[0].id = cudaLaunchAttributeProgrammaticStreamSerialization;
    attrs[0].val.programmaticStreamSerializationAllowed = 1;
    cfg.attrs = attrs;
    cfg.numAttrs = 1;
    cudaLaunchKernelEx(&cfg, render_kernel, out);
}